// round 6
// baseline (speedup 1.0000x reference)
#include <cuda_runtime.h>
#include <math.h>

#define Bc 8
#define Sc 2048
#define Dc 1024
#define Hc 4
#define HDc 256
#define ROWS_PER_BLK 32
#define NBLK ((Bc * Sc) / ROWS_PER_BLK)   // 512
#define MIDBLK 128

// ---------------- scratch (static device memory; no allocation) -------------
__device__ float4 g_rowstats[Bc * Sc];      // (mu_t, rstd_t, mu_i, rstd_i)
__device__ float  g_partial[NBLK * 2048];   // per-block sum of tn | in (4 MB)
__device__ float  g_simpart[NBLK];
__device__ float  g_sums[Bc * 2048];        // text_global | image_global (already /S)
__device__ float  g_globalsim[Bc];
__device__ float  g_gates[Bc * Hc * HDc];
__device__ float  g_gate[Bc];
__device__ unsigned g_barcnt = 0;
__device__ unsigned g_bargen = 0;

__device__ __forceinline__ float bfly(float v) {
#pragma unroll
    for (int o = 16; o > 0; o >>= 1) v += __shfl_xor_sync(0xffffffffu, v, o);
    return v;
}

// Grid-wide barrier. Requires all nblk CTAs co-resident.
__device__ __forceinline__ void grid_barrier(unsigned nblk) {
    __syncthreads();
    if (threadIdx.x == 0) {
        __threadfence();
        const unsigned gen = atomicAdd(&g_bargen, 0u);
        __threadfence();
        if (atomicAdd(&g_barcnt, 1u) == nblk - 1u) {
            atomicExch(&g_barcnt, 0u);
            __threadfence();
            atomicAdd(&g_bargen, 1u);
        } else {
            while (atomicAdd(&g_bargen, 0u) == gen) { }
        }
        __threadfence();
    }
    __syncthreads();
}

// ---------------- pass 1: warp-per-row, two-phase (L1 re-read), no barriers -
// Phase A: stream row, keep only 4 scalar sums -> mu, rstd (warp bfly).
// Phase B: re-read row (L1-hot), normalize, accumulate vt/vi + sim dots.
__global__ void __launch_bounds__(256, 2) k_stats(
    const float* __restrict__ xt, const float* __restrict__ xi,
    const float* __restrict__ ltw, const float* __restrict__ ltb,
    const float* __restrict__ liw, const float* __restrict__ lib)
{
    __shared__ float sm[8192];   // [wt|bt|wi|bi] during loop, 4 combine slices after
    __shared__ float s_sim[8];

    const int tid = threadIdx.x, lane = tid & 31, warp = tid >> 5;

    for (int j = tid; j < 1024; j += 256) {
        sm[j]        = ltw[j];
        sm[1024 + j] = ltb[j];
        sm[2048 + j] = liw[j];
        sm[3072 + j] = lib[j];
    }
    __syncthreads();

    const int blk = blockIdx.x;
    const float4* xt4 = reinterpret_cast<const float4*>(xt);
    const float4* xi4 = reinterpret_cast<const float4*>(xi);

    float4 vt[8], vi[8];
#pragma unroll
    for (int g = 0; g < 8; g++) {
        vt[g] = make_float4(0.f, 0.f, 0.f, 0.f);
        vi[g] = make_float4(0.f, 0.f, 0.f, 0.f);
    }
    float sim_acc = 0.f;

    for (int r = 0; r < 4; r++) {
        const int row  = blk * ROWS_PER_BLK + warp * 4 + r;
        const int base = row * 256 + lane;       // float4 index

        // ---- Phase A: stats only (nothing else live -> loads front-batch) ----
        float sa = 0.f, saa = 0.f, sc = 0.f, scc = 0.f;
#pragma unroll
        for (int half = 0; half < 2; half++) {
            float4 A[4], C[4];
#pragma unroll
            for (int g = 0; g < 4; g++) {
                A[g] = xt4[base + (half * 4 + g) * 32];
                C[g] = xi4[base + (half * 4 + g) * 32];
            }
#pragma unroll
            for (int g = 0; g < 4; g++) {
                sa += A[g].x; saa = fmaf(A[g].x, A[g].x, saa);
                sa += A[g].y; saa = fmaf(A[g].y, A[g].y, saa);
                sa += A[g].z; saa = fmaf(A[g].z, A[g].z, saa);
                sa += A[g].w; saa = fmaf(A[g].w, A[g].w, saa);
                sc += C[g].x; scc = fmaf(C[g].x, C[g].x, scc);
                sc += C[g].y; scc = fmaf(C[g].y, C[g].y, scc);
                sc += C[g].z; scc = fmaf(C[g].z, C[g].z, scc);
                sc += C[g].w; scc = fmaf(C[g].w, C[g].w, scc);
            }
        }
        sa = bfly(sa); saa = bfly(saa); sc = bfly(sc); scc = bfly(scc);

        const float mut = sa * (1.f / 1024.f);
        const float rt  = rsqrtf(fmaxf(saa * (1.f / 1024.f) - mut * mut, 0.f) + 1e-5f);
        const float mui = sc * (1.f / 1024.f);
        const float ri  = rsqrtf(fmaxf(scc * (1.f / 1024.f) - mui * mui, 0.f) + 1e-5f);
        if (lane == 0) g_rowstats[row] = make_float4(mut, rt, mui, ri);

        // ---- Phase B: re-read (L1 hits), normalize, accumulate ----
        const float nmt = -rt * mut, nmi = -ri * mui;
        float tt = 0.f, ii = 0.f, ti = 0.f;
#pragma unroll
        for (int g = 0; g < 8; g++) {
            const float4 a = xt4[base + g * 32];
            const float4 c = xi4[base + g * 32];
            const int o = g * 128 + lane * 4;
            const float4 w_t = *reinterpret_cast<float4*>(&sm[o]);
            const float4 b_t = *reinterpret_cast<float4*>(&sm[1024 + o]);
            const float4 w_i = *reinterpret_cast<float4*>(&sm[2048 + o]);
            const float4 b_i = *reinterpret_cast<float4*>(&sm[3072 + o]);

            float f, h2, tn, in;
            f  = fmaf(a.x, rt, nmt);  tn = fmaf(f, w_t.x, b_t.x);
            h2 = fmaf(c.x, ri, nmi);  in = fmaf(h2, w_i.x, b_i.x);
            tt = fmaf(tn, tn, tt); ii = fmaf(in, in, ii); ti = fmaf(tn, in, ti);
            vt[g].x += tn; vi[g].x += in;

            f  = fmaf(a.y, rt, nmt);  tn = fmaf(f, w_t.y, b_t.y);
            h2 = fmaf(c.y, ri, nmi);  in = fmaf(h2, w_i.y, b_i.y);
            tt = fmaf(tn, tn, tt); ii = fmaf(in, in, ii); ti = fmaf(tn, in, ti);
            vt[g].y += tn; vi[g].y += in;

            f  = fmaf(a.z, rt, nmt);  tn = fmaf(f, w_t.z, b_t.z);
            h2 = fmaf(c.z, ri, nmi);  in = fmaf(h2, w_i.z, b_i.z);
            tt = fmaf(tn, tn, tt); ii = fmaf(in, in, ii); ti = fmaf(tn, in, ti);
            vt[g].z += tn; vi[g].z += in;

            f  = fmaf(a.w, rt, nmt);  tn = fmaf(f, w_t.w, b_t.w);
            h2 = fmaf(c.w, ri, nmi);  in = fmaf(h2, w_i.w, b_i.w);
            tt = fmaf(tn, tn, tt); ii = fmaf(in, in, ii); ti = fmaf(tn, in, ti);
            vt[g].w += tn; vi[g].w += in;
        }
        tt = bfly(tt); ii = bfly(ii); ti = bfly(ti);
        sim_acc += ti / (fmaxf(sqrtf(tt), 1e-6f) * fmaxf(sqrtf(ii), 1e-6f));
    }

    if (lane == 0) s_sim[warp] = sim_acc;
    __syncthreads();    // weights dead; reuse sm as 4 combine slices

    float* slice = sm + (warp & 3) * 2048;
    if (warp < 4) {
#pragma unroll
        for (int g = 0; g < 8; g++) {
            *reinterpret_cast<float4*>(&slice[g * 128 + lane * 4])        = vt[g];
            *reinterpret_cast<float4*>(&slice[1024 + g * 128 + lane * 4]) = vi[g];
        }
    }
    __syncthreads();
    if (warp >= 4) {
#pragma unroll
        for (int g = 0; g < 8; g++) {
            float4* p = reinterpret_cast<float4*>(&slice[g * 128 + lane * 4]);
            float4 v = *p;
            v.x += vt[g].x; v.y += vt[g].y; v.z += vt[g].z; v.w += vt[g].w;
            *p = v;
            float4* q = reinterpret_cast<float4*>(&slice[1024 + g * 128 + lane * 4]);
            float4 u = *q;
            u.x += vi[g].x; u.y += vi[g].y; u.z += vi[g].z; u.w += vi[g].w;
            *q = u;
        }
    }
    __syncthreads();
    for (int j = tid; j < 2048; j += 256)
        g_partial[blk * 2048 + j] = (sm[j] + sm[2048 + j]) + (sm[4096 + j] + sm[6144 + j]);
    if (tid == 0) {
        float s = 0.f;
#pragma unroll
        for (int w = 0; w < 8; w++) s += s_sim[w];
        g_simpart[blk] = s;
    }
}

// ---------------- pass 2 (fused): reduce -> gates -> fc ---------------------
__global__ void __launch_bounds__(256) k_mid(
    const float* __restrict__ Wa, const float* __restrict__ Wab,
    const float* __restrict__ Wq, const float* __restrict__ Wqb,
    const float* __restrict__ simw, const float* __restrict__ simb,
    const float* __restrict__ fcw, const float* __restrict__ fcb)
{
    const int tid = threadIdx.x, bi = blockIdx.x;
    const int warp = tid >> 5, lane = tid & 31;
    __shared__ float red[256];

    // ---- Phase A: fold 64 partials per slot (128 slots per block) ----
    {
        const int j = bi * 128 + (tid & 127);       // global slot 0..16383
        const int half = tid >> 7;                  // 0 or 1
        const int b = j >> 11, slot = j & 2047;
        float s = 0.f;
#pragma unroll 8
        for (int p = half * 32; p < half * 32 + 32; p++)
            s += g_partial[(b * 64 + p) * 2048 + slot];
        red[tid] = s;
        __syncthreads();
        if (tid < 128) g_sums[j] = (red[tid] + red[tid + 128]) * (1.f / (float)Sc);
    }
    if (bi == 0) {   // sim reduce: warp w handles batch w
        float v = g_simpart[warp * 64 + lane] + g_simpart[warp * 64 + 32 + lane];
        v = bfly(v);
        if (lane == 0) g_globalsim[warp] = v * (1.f / (float)Sc);
    }

    grid_barrier(MIDBLK);

    // ---- Phase B: gate GEMV, warp-per-hk, all 8 batches per warp ----
    {
        const int hk = bi * 8 + warp;      // 0..1023
        const int k  = hk & 255;

        const float4* wa = reinterpret_cast<const float4*>(Wa + (size_t)hk * 1024);
        const float4* wq = reinterpret_cast<const float4*>(Wq + (size_t)hk * 1024);

        float4 wA[8], wQ[8];
#pragma unroll
        for (int g = 0; g < 8; g++) {
            wA[g] = __ldg(&wa[g * 32 + lane]);
            wQ[g] = __ldg(&wq[g * 32 + lane]);
        }

        float da[Bc], dq[Bc];
#pragma unroll
        for (int b = 0; b < Bc; b++) { da[b] = 0.f; dq[b] = 0.f; }

#pragma unroll
        for (int b = 0; b < Bc; b++) {
            const float4* tg = reinterpret_cast<const float4*>(g_sums + b * 2048);
            const float4* ig = tg + 256;
#pragma unroll
            for (int g = 0; g < 8; g++) {
                const float4 t = __ldg(&tg[g * 32 + lane]);
                const float4 i = __ldg(&ig[g * 32 + lane]);
                da[b] = fmaf(wA[g].x, t.x, da[b]); da[b] = fmaf(wA[g].y, t.y, da[b]);
                da[b] = fmaf(wA[g].z, t.z, da[b]); da[b] = fmaf(wA[g].w, t.w, da[b]);
                dq[b] = fmaf(wQ[g].x, i.x, dq[b]); dq[b] = fmaf(wQ[g].y, i.y, dq[b]);
                dq[b] = fmaf(wQ[g].z, i.z, dq[b]); dq[b] = fmaf(wQ[g].w, i.w, dq[b]);
            }
        }
#pragma unroll
        for (int b = 0; b < Bc; b++) { da[b] = bfly(da[b]); dq[b] = bfly(dq[b]); }

        if (lane == 0) {
            const float wab = Wab[hk], wqb = Wqb[hk];
            const float sw = simw[k], sb = simb[k];
#pragma unroll
            for (int b = 0; b < Bc; b++) {
                const float gate = da[b] + wab + dq[b] + wqb + g_globalsim[b] * sw + sb;
                g_gates[b * 1024 + hk] = fmaxf(gate, 0.f);
            }
        }
    }

    grid_barrier(MIDBLK);

    // ---- Phase C: fc dot + sigmoid, blocks 0..7 (block b = batch b) ----
    if (bi < Bc) {
        float acc = 0.f;
#pragma unroll
        for (int k = tid; k < 1024; k += 256) acc += g_gates[bi * 1024 + k] * fcw[k];
        acc = bfly(acc);
        if (lane == 0) red[warp] = acc;
        __syncthreads();
        if (tid == 0) {
            float s = 0.f;
#pragma unroll
            for (int w = 0; w < 8; w++) s += red[w];
            g_gate[bi] = 1.0f / (1.0f + expf(-(s + fcb[0])));
        }
    }
}

// ---------------- pass 3: out = g*LN(t) + (1-g)*LN(i) -----------------------
__global__ void __launch_bounds__(256) k_out(
    const float* __restrict__ xt, const float* __restrict__ xi,
    const float* __restrict__ ltw, const float* __restrict__ ltb,
    const float* __restrict__ liw, const float* __restrict__ lib,
    float* __restrict__ out)
{
    const int t = threadIdx.x;
    const float4 wt = reinterpret_cast<const float4*>(ltw)[t];
    const float4 bt = reinterpret_cast<const float4*>(ltb)[t];
    const float4 wi = reinterpret_cast<const float4*>(liw)[t];
    const float4 bi = reinterpret_cast<const float4*>(lib)[t];
    const float4* xt4 = reinterpret_cast<const float4*>(xt);
    const float4* xi4 = reinterpret_cast<const float4*>(xi);
    float4* o4 = reinterpret_cast<float4*>(out);

    const int row0 = (int)blockIdx.x * 4;
#pragma unroll
    for (int r = 0; r < 4; r++) {
        const int row = row0 + r;
        const float4 rs = g_rowstats[row];
        const float g  = g_gate[row >> 11];
        const float gm = 1.0f - g;
        const int idx  = row * 256 + t;
        const float4 a = __ldcs(&xt4[idx]);
        const float4 c = __ldcs(&xi4[idx]);
        float4 o;
        o.x = g * ((a.x - rs.x) * rs.y * wt.x + bt.x) + gm * ((c.x - rs.z) * rs.w * wi.x + bi.x);
        o.y = g * ((a.y - rs.x) * rs.y * wt.y + bt.y) + gm * ((c.y - rs.z) * rs.w * wi.y + bi.y);
        o.z = g * ((a.z - rs.x) * rs.y * wt.z + bt.z) + gm * ((c.z - rs.z) * rs.w * wi.z + bi.z);
        o.w = g * ((a.w - rs.x) * rs.y * wt.w + bt.w) + gm * ((c.w - rs.z) * rs.w * wi.w + bi.w);
        __stcs(&o4[idx], o);
    }
}

// ---------------- launch -----------------------------------------------------
extern "C" void kernel_launch(void* const* d_in, const int* in_sizes, int n_in,
                              void* d_out, int out_size)
{
    const float* xt   = (const float*)d_in[0];
    const float* xi   = (const float*)d_in[1];
    const float* ltw  = (const float*)d_in[2];
    const float* ltb  = (const float*)d_in[3];
    const float* liw  = (const float*)d_in[4];
    const float* lib  = (const float*)d_in[5];
    const float* Wa   = (const float*)d_in[6];
    const float* Wab  = (const float*)d_in[7];
    const float* Wq   = (const float*)d_in[8];
    const float* Wqb  = (const float*)d_in[9];
    const float* simw = (const float*)d_in[10];
    const float* simb = (const float*)d_in[11];
    const float* fcw  = (const float*)d_in[12];
    const float* fcb  = (const float*)d_in[13];
    float* out = (float*)d_out;

    k_stats<<<NBLK, 256>>>(xt, xi, ltw, ltb, liw, lib);
    k_mid  <<<MIDBLK, 256>>>(Wa, Wab, Wq, Wqb, simw, simb, fcw, fcb);
    k_out  <<<(Bc * Sc) / 4, 256>>>(xt, xi, ltw, ltb, liw, lib, out);
}

// round 7
// speedup vs baseline: 1.0316x; 1.0316x over previous
#include <cuda_runtime.h>
#include <math.h>
#include <stdint.h>

#define Bc 8
#define Sc 2048
#define Dc 1024
#define Hc 4
#define HDc 256
#define ROWS_PER_BLK 32
#define NBLK ((Bc * Sc) / ROWS_PER_BLK)   // 512
#define MIDBLK 128

// k_stats dynamic smem layout (floats):
//   [0, 4096)            weights wt|bt|wi|bi   (16 KB) ; reused for combine slices
//   [4096, 4096+32768)   2 stages x 2 tensors x 8 rows x 1024 floats (128 KB)
//   tail: 2 mbarriers
#define SMW 0
#define SMBUF 4096
#define STAGE_FLOATS 16384        // one stage: 2 tensors x 8192 floats
#define MBAR_BYTE_OFF (4096 * 4 + 2 * STAGE_FLOATS * 4)   // 147456
#define SMEM_BYTES (MBAR_BYTE_OFF + 64)

// ---------------- scratch (static device memory; no allocation) -------------
__device__ float4 g_rowstats[Bc * Sc];      // (mu_t, rstd_t, mu_i, rstd_i)
__device__ float  g_partial[NBLK * 2048];   // per-block sum of tn | in (4 MB)
__device__ float  g_simpart[NBLK];
__device__ float  g_sums[Bc * 2048];        // text_global | image_global (already /S)
__device__ float  g_globalsim[Bc];
__device__ float  g_gates[Bc * Hc * HDc];
__device__ float  g_gate[Bc];
__device__ unsigned g_barcnt = 0;
__device__ unsigned g_bargen = 0;

__device__ __forceinline__ float bfly(float v) {
#pragma unroll
    for (int o = 16; o > 0; o >>= 1) v += __shfl_xor_sync(0xffffffffu, v, o);
    return v;
}

__device__ __forceinline__ uint32_t smem_u32(const void* p) {
    uint32_t a;
    asm("{ .reg .u64 t; cvta.to.shared.u64 t, %1; cvt.u32.u64 %0, t; }" : "=r"(a) : "l"(p));
    return a;
}
__device__ __forceinline__ void mbar_init(uint32_t a, uint32_t cnt) {
    asm volatile("mbarrier.init.shared.b64 [%0], %1;" :: "r"(a), "r"(cnt) : "memory");
}
__device__ __forceinline__ void mbar_expect_tx(uint32_t a, uint32_t bytes) {
    asm volatile("mbarrier.arrive.expect_tx.shared.b64 _, [%0], %1;" :: "r"(a), "r"(bytes) : "memory");
}
__device__ __forceinline__ void bulk_g2s(uint32_t dst, const void* src, uint32_t bytes, uint32_t mbar) {
    asm volatile("cp.async.bulk.shared::cluster.global.mbarrier::complete_tx::bytes [%0], [%1], %2, [%3];"
                 :: "r"(dst), "l"(src), "r"(bytes), "r"(mbar) : "memory");
}
__device__ __forceinline__ void mbar_wait(uint32_t a, uint32_t parity) {
    uint32_t done;
    asm volatile(
        "{\n\t.reg .pred p;\n\t"
        "mbarrier.try_wait.parity.acquire.cta.shared::cta.b64 p, [%1], %2;\n\t"
        "selp.b32 %0, 1, 0, p;\n\t}"
        : "=r"(done) : "r"(a), "r"(parity) : "memory");
    if (!done) {
        asm volatile(
            "{\n\t.reg .pred P1;\n\t"
            "W%=:\n\t"
            "mbarrier.try_wait.parity.acquire.cta.shared::cta.b64 P1, [%0], %1, 0x989680;\n\t"
            "@P1 bra.uni D%=;\n\t"
            "bra.uni W%=;\n\t"
            "D%=:\n\t}"
            :: "r"(a), "r"(parity) : "memory");
    }
}

// Grid-wide barrier. Requires all nblk CTAs co-resident.
__device__ __forceinline__ void grid_barrier(unsigned nblk) {
    __syncthreads();
    if (threadIdx.x == 0) {
        __threadfence();
        const unsigned gen = atomicAdd(&g_bargen, 0u);
        __threadfence();
        if (atomicAdd(&g_barcnt, 1u) == nblk - 1u) {
            atomicExch(&g_barcnt, 0u);
            __threadfence();
            atomicAdd(&g_bargen, 1u);
        } else {
            while (atomicAdd(&g_bargen, 0u) == gen) { }
        }
        __threadfence();
    }
    __syncthreads();
}

// ---------------- pass 1: bulk-copy pipelined LN stats ----------------------
// DRAM side: cp.async.bulk double-buffered stream (decoupled from compute).
// Compute side: warp-per-row from SMEM, 4 stages x 8 rows.
__global__ void __launch_bounds__(256) k_stats(
    const float* __restrict__ xt, const float* __restrict__ xi,
    const float* __restrict__ ltw, const float* __restrict__ ltb,
    const float* __restrict__ liw, const float* __restrict__ lib)
{
    extern __shared__ __align__(1024) char dynsm[];
    float* sm = reinterpret_cast<float*>(dynsm);          // weights
    __shared__ float s_sim[8];

    const int tid = threadIdx.x, lane = tid & 31, warp = tid >> 5;
    const int blk = blockIdx.x;

    const uint32_t smem_base = smem_u32(dynsm);
    const uint32_t mb0 = smem_base + MBAR_BYTE_OFF;
    const uint32_t mb1 = mb0 + 8;

    // init mbarriers + stage-0/1 copies
    if (tid == 0) {
        mbar_init(mb0, 1);
        mbar_init(mb1, 1);
    }
    // weights into smem (overlaps with bulk copies in flight)
    for (int j = tid; j < 1024; j += 256) {
        sm[SMW + j]        = ltw[j];
        sm[SMW + 1024 + j] = ltb[j];
        sm[SMW + 2048 + j] = liw[j];
        sm[SMW + 3072 + j] = lib[j];
    }
    __syncthreads();
    if (tid == 0) {
        const float* srcT = xt + (size_t)blk * ROWS_PER_BLK * 1024;
        const float* srcI = xi + (size_t)blk * ROWS_PER_BLK * 1024;
#pragma unroll
        for (int s = 0; s < 2; s++) {
            const uint32_t mb = s ? mb1 : mb0;
            mbar_expect_tx(mb, 65536);
            const uint32_t dst = smem_base + (SMBUF + s * STAGE_FLOATS) * 4;
            bulk_g2s(dst,        srcT + s * 8192, 32768, mb);
            bulk_g2s(dst + 32768, srcI + s * 8192, 32768, mb);
        }
    }

    float4 vt[8], vi[8];
#pragma unroll
    for (int g = 0; g < 8; g++) {
        vt[g] = make_float4(0.f, 0.f, 0.f, 0.f);
        vi[g] = make_float4(0.f, 0.f, 0.f, 0.f);
    }
    float sim_acc = 0.f;

    for (int st = 0; st < 4; st++) {
        const uint32_t mb = (st & 1) ? mb1 : mb0;
        mbar_wait(mb, st >> 1);

        const float* bufT = sm + SMBUF + (st & 1) * STAGE_FLOATS + warp * 1024;
        const float* bufI = bufT + 8192;
        const float4* A4 = reinterpret_cast<const float4*>(bufT);
        const float4* C4 = reinterpret_cast<const float4*>(bufI);
        const int row = blk * ROWS_PER_BLK + st * 8 + warp;

        // ---- Phase A: moments from smem ----
        float sa = 0.f, saa = 0.f, sc = 0.f, scc = 0.f;
#pragma unroll
        for (int g = 0; g < 8; g++) {
            const float4 a = A4[g * 32 + lane];
            const float4 c = C4[g * 32 + lane];
            sa += a.x; saa = fmaf(a.x, a.x, saa);
            sa += a.y; saa = fmaf(a.y, a.y, saa);
            sa += a.z; saa = fmaf(a.z, a.z, saa);
            sa += a.w; saa = fmaf(a.w, a.w, saa);
            sc += c.x; scc = fmaf(c.x, c.x, scc);
            sc += c.y; scc = fmaf(c.y, c.y, scc);
            sc += c.z; scc = fmaf(c.z, c.z, scc);
            sc += c.w; scc = fmaf(c.w, c.w, scc);
        }
        sa = bfly(sa); saa = bfly(saa); sc = bfly(sc); scc = bfly(scc);

        const float mut = sa * (1.f / 1024.f);
        const float rt  = rsqrtf(fmaxf(saa * (1.f / 1024.f) - mut * mut, 0.f) + 1e-5f);
        const float mui = sc * (1.f / 1024.f);
        const float ri  = rsqrtf(fmaxf(scc * (1.f / 1024.f) - mui * mui, 0.f) + 1e-5f);
        if (lane == 0) g_rowstats[row] = make_float4(mut, rt, mui, ri);

        // ---- Phase B: normalize from smem, accumulate ----
        const float nmt = -rt * mut, nmi = -ri * mui;
        float tt = 0.f, ii = 0.f, ti = 0.f;
#pragma unroll
        for (int g = 0; g < 8; g++) {
            const float4 a = A4[g * 32 + lane];
            const float4 c = C4[g * 32 + lane];
            const int o = g * 128 + lane * 4;
            const float4 w_t = *reinterpret_cast<const float4*>(&sm[SMW + o]);
            const float4 b_t = *reinterpret_cast<const float4*>(&sm[SMW + 1024 + o]);
            const float4 w_i = *reinterpret_cast<const float4*>(&sm[SMW + 2048 + o]);
            const float4 b_i = *reinterpret_cast<const float4*>(&sm[SMW + 3072 + o]);

            float f, h2, tn, in;
            f  = fmaf(a.x, rt, nmt);  tn = fmaf(f, w_t.x, b_t.x);
            h2 = fmaf(c.x, ri, nmi);  in = fmaf(h2, w_i.x, b_i.x);
            tt = fmaf(tn, tn, tt); ii = fmaf(in, in, ii); ti = fmaf(tn, in, ti);
            vt[g].x += tn; vi[g].x += in;

            f  = fmaf(a.y, rt, nmt);  tn = fmaf(f, w_t.y, b_t.y);
            h2 = fmaf(c.y, ri, nmi);  in = fmaf(h2, w_i.y, b_i.y);
            tt = fmaf(tn, tn, tt); ii = fmaf(in, in, ii); ti = fmaf(tn, in, ti);
            vt[g].y += tn; vi[g].y += in;

            f  = fmaf(a.z, rt, nmt);  tn = fmaf(f, w_t.z, b_t.z);
            h2 = fmaf(c.z, ri, nmi);  in = fmaf(h2, w_i.z, b_i.z);
            tt = fmaf(tn, tn, tt); ii = fmaf(in, in, ii); ti = fmaf(tn, in, ti);
            vt[g].z += tn; vi[g].z += in;

            f  = fmaf(a.w, rt, nmt);  tn = fmaf(f, w_t.w, b_t.w);
            h2 = fmaf(c.w, ri, nmi);  in = fmaf(h2, w_i.w, b_i.w);
            tt = fmaf(tn, tn, tt); ii = fmaf(in, in, ii); ti = fmaf(tn, in, ti);
            vt[g].w += tn; vi[g].w += in;
        }
        tt = bfly(tt); ii = bfly(ii); ti = bfly(ti);
        sim_acc += ti / (fmaxf(sqrtf(tt), 1e-6f) * fmaxf(sqrtf(ii), 1e-6f));

        // stage consumed; reissue this buffer for stage st+2
        __syncthreads();
        if (tid == 0 && st < 2) {
            const float* srcT = xt + (size_t)blk * ROWS_PER_BLK * 1024 + (st + 2) * 8192;
            const float* srcI = xi + (size_t)blk * ROWS_PER_BLK * 1024 + (st + 2) * 8192;
            mbar_expect_tx(mb, 65536);
            const uint32_t dst = smem_base + (SMBUF + (st & 1) * STAGE_FLOATS) * 4;
            bulk_g2s(dst,         srcT, 32768, mb);
            bulk_g2s(dst + 32768, srcI, 32768, mb);
        }
    }

    if (lane == 0) s_sim[warp] = sim_acc;
    __syncthreads();    // buffers dead; combine in buf region (4 slices x 2048)

    float* slice = sm + SMBUF + (warp & 3) * 2048;
    if (warp < 4) {
#pragma unroll
        for (int g = 0; g < 8; g++) {
            *reinterpret_cast<float4*>(&slice[g * 128 + lane * 4])        = vt[g];
            *reinterpret_cast<float4*>(&slice[1024 + g * 128 + lane * 4]) = vi[g];
        }
    }
    __syncthreads();
    if (warp >= 4) {
#pragma unroll
        for (int g = 0; g < 8; g++) {
            float4* p = reinterpret_cast<float4*>(&slice[g * 128 + lane * 4]);
            float4 v = *p;
            v.x += vt[g].x; v.y += vt[g].y; v.z += vt[g].z; v.w += vt[g].w;
            *p = v;
            float4* q = reinterpret_cast<float4*>(&slice[1024 + g * 128 + lane * 4]);
            float4 u = *q;
            u.x += vi[g].x; u.y += vi[g].y; u.z += vi[g].z; u.w += vi[g].w;
            *q = u;
        }
    }
    __syncthreads();
    for (int j = tid; j < 2048; j += 256)
        g_partial[blk * 2048 + j] = (sm[SMBUF + j] + sm[SMBUF + 2048 + j])
                                  + (sm[SMBUF + 4096 + j] + sm[SMBUF + 6144 + j]);
    if (tid == 0) {
        float s = 0.f;
#pragma unroll
        for (int w = 0; w < 8; w++) s += s_sim[w];
        g_simpart[blk] = s;
    }
}

// ---------------- pass 2 (fused): reduce -> gates -> fc ---------------------
__global__ void __launch_bounds__(256) k_mid(
    const float* __restrict__ Wa, const float* __restrict__ Wab,
    const float* __restrict__ Wq, const float* __restrict__ Wqb,
    const float* __restrict__ simw, const float* __restrict__ simb,
    const float* __restrict__ fcw, const float* __restrict__ fcb)
{
    const int tid = threadIdx.x, bi = blockIdx.x;
    const int warp = tid >> 5, lane = tid & 31;
    __shared__ float red[256];

    {
        const int j = bi * 128 + (tid & 127);
        const int half = tid >> 7;
        const int b = j >> 11, slot = j & 2047;
        float s = 0.f;
#pragma unroll 8
        for (int p = half * 32; p < half * 32 + 32; p++)
            s += g_partial[(b * 64 + p) * 2048 + slot];
        red[tid] = s;
        __syncthreads();
        if (tid < 128) g_sums[j] = (red[tid] + red[tid + 128]) * (1.f / (float)Sc);
    }
    if (bi == 0) {
        float v = g_simpart[warp * 64 + lane] + g_simpart[warp * 64 + 32 + lane];
        v = bfly(v);
        if (lane == 0) g_globalsim[warp] = v * (1.f / (float)Sc);
    }

    grid_barrier(MIDBLK);

    {
        const int hk = bi * 8 + warp;
        const int k  = hk & 255;

        const float4* wa = reinterpret_cast<const float4*>(Wa + (size_t)hk * 1024);
        const float4* wq = reinterpret_cast<const float4*>(Wq + (size_t)hk * 1024);

        float4 wA[8], wQ[8];
#pragma unroll
        for (int g = 0; g < 8; g++) {
            wA[g] = __ldg(&wa[g * 32 + lane]);
            wQ[g] = __ldg(&wq[g * 32 + lane]);
        }

        float da[Bc], dq[Bc];
#pragma unroll
        for (int b = 0; b < Bc; b++) { da[b] = 0.f; dq[b] = 0.f; }

#pragma unroll
        for (int b = 0; b < Bc; b++) {
            const float4* tg = reinterpret_cast<const float4*>(g_sums + b * 2048);
            const float4* ig = tg + 256;
#pragma unroll
            for (int g = 0; g < 8; g++) {
                const float4 t = __ldg(&tg[g * 32 + lane]);
                const float4 i = __ldg(&ig[g * 32 + lane]);
                da[b] = fmaf(wA[g].x, t.x, da[b]); da[b] = fmaf(wA[g].y, t.y, da[b]);
                da[b] = fmaf(wA[g].z, t.z, da[b]); da[b] = fmaf(wA[g].w, t.w, da[b]);
                dq[b] = fmaf(wQ[g].x, i.x, dq[b]); dq[b] = fmaf(wQ[g].y, i.y, dq[b]);
                dq[b] = fmaf(wQ[g].z, i.z, dq[b]); dq[b] = fmaf(wQ[g].w, i.w, dq[b]);
            }
        }
#pragma unroll
        for (int b = 0; b < Bc; b++) { da[b] = bfly(da[b]); dq[b] = bfly(dq[b]); }

        if (lane == 0) {
            const float wab = Wab[hk], wqb = Wqb[hk];
            const float sw = simw[k], sb = simb[k];
#pragma unroll
            for (int b = 0; b < Bc; b++) {
                const float gate = da[b] + wab + dq[b] + wqb + g_globalsim[b] * sw + sb;
                g_gates[b * 1024 + hk] = fmaxf(gate, 0.f);
            }
        }
    }

    grid_barrier(MIDBLK);

    if (bi < Bc) {
        float acc = 0.f;
#pragma unroll
        for (int k = tid; k < 1024; k += 256) acc += g_gates[bi * 1024 + k] * fcw[k];
        acc = bfly(acc);
        if (lane == 0) red[warp] = acc;
        __syncthreads();
        if (tid == 0) {
            float s = 0.f;
#pragma unroll
            for (int w = 0; w < 8; w++) s += red[w];
            g_gate[bi] = 1.0f / (1.0f + expf(-(s + fcb[0])));
        }
    }
}

// ---------------- pass 3: out = g*LN(t) + (1-g)*LN(i) -----------------------
__global__ void __launch_bounds__(256) k_out(
    const float* __restrict__ xt, const float* __restrict__ xi,
    const float* __restrict__ ltw, const float* __restrict__ ltb,
    const float* __restrict__ liw, const float* __restrict__ lib,
    float* __restrict__ out)
{
    const int t = threadIdx.x;
    const float4 wt = reinterpret_cast<const float4*>(ltw)[t];
    const float4 bt = reinterpret_cast<const float4*>(ltb)[t];
    const float4 wi = reinterpret_cast<const float4*>(liw)[t];
    const float4 bi = reinterpret_cast<const float4*>(lib)[t];
    const float4* xt4 = reinterpret_cast<const float4*>(xt);
    const float4* xi4 = reinterpret_cast<const float4*>(xi);
    float4* o4 = reinterpret_cast<float4*>(out);

    const int row0 = (int)blockIdx.x * 4;
#pragma unroll
    for (int r = 0; r < 4; r++) {
        const int row = row0 + r;
        const float4 rs = g_rowstats[row];
        const float g  = g_gate[row >> 11];
        const float gm = 1.0f - g;
        const int idx  = row * 256 + t;
        const float4 a = __ldcs(&xt4[idx]);
        const float4 c = __ldcs(&xi4[idx]);
        float4 o;
        o.x = g * ((a.x - rs.x) * rs.y * wt.x + bt.x) + gm * ((c.x - rs.z) * rs.w * wi.x + bi.x);
        o.y = g * ((a.y - rs.x) * rs.y * wt.y + bt.y) + gm * ((c.y - rs.z) * rs.w * wi.y + bi.y);
        o.z = g * ((a.z - rs.x) * rs.y * wt.z + bt.z) + gm * ((c.z - rs.z) * rs.w * wi.z + bi.z);
        o.w = g * ((a.w - rs.x) * rs.y * wt.w + bt.w) + gm * ((c.w - rs.z) * rs.w * wi.w + bi.w);
        __stcs(&o4[idx], o);
    }
}

// ---------------- launch -----------------------------------------------------
extern "C" void kernel_launch(void* const* d_in, const int* in_sizes, int n_in,
                              void* d_out, int out_size)
{
    const float* xt   = (const float*)d_in[0];
    const float* xi   = (const float*)d_in[1];
    const float* ltw  = (const float*)d_in[2];
    const float* ltb  = (const float*)d_in[3];
    const float* liw  = (const float*)d_in[4];
    const float* lib  = (const float*)d_in[5];
    const float* Wa   = (const float*)d_in[6];
    const float* Wab  = (const float*)d_in[7];
    const float* Wq   = (const float*)d_in[8];
    const float* Wqb  = (const float*)d_in[9];
    const float* simw = (const float*)d_in[10];
    const float* simb = (const float*)d_in[11];
    const float* fcw  = (const float*)d_in[12];
    const float* fcb  = (const float*)d_in[13];
    float* out = (float*)d_out;

    static bool attr_set = false;
    if (!attr_set) {
        cudaFuncSetAttribute(k_stats, cudaFuncAttributeMaxDynamicSharedMemorySize, SMEM_BYTES);
        attr_set = true;
    }

    k_stats<<<NBLK, 256, SMEM_BYTES>>>(xt, xi, ltw, ltb, liw, lib);
    k_mid  <<<MIDBLK, 256>>>(Wa, Wab, Wq, Wqb, simw, simb, fcw, fcb);
    k_out  <<<(Bc * Sc) / 4, 256>>>(xt, xi, ltw, ltb, liw, lib, out);
}

// round 8
// speedup vs baseline: 1.1401x; 1.1052x over previous
#include <cuda_runtime.h>
#include <math.h>
#include <stdint.h>

#define Bc 8
#define Sc 2048
#define Dc 1024
#define Hc 4
#define HDc 256
#define NCTA 128                 // persistent single-wave grid for k_stats
#define ROWS_PER_CTA 128         // contiguous rows, all in one batch
#define NSTAGE 16                // 16 stages x 8 rows
#define RING 3
#define MIDBLK 128

// k_stats dynamic smem layout (floats):
//   [0, 4096)                 weights wt|bt|wi|bi (16 KB); combine reuses buffers
//   [4096, 4096+3*16384)      3 ring slots x (2 tensors x 8 rows x 1024) (192 KB)
//   tail: 3 mbarriers
#define SMW 0
#define SMBUF 4096
#define STAGE_FLOATS 16384
#define MBAR_BYTE_OFF ((4096 + RING * STAGE_FLOATS) * 4)   // 212992
#define SMEM_BYTES (MBAR_BYTE_OFF + 64)

// ---------------- scratch (static device memory; no allocation) -------------
__device__ float4 g_rowstats[Bc * Sc];      // (mu_t, rstd_t, mu_i, rstd_i)
__device__ float  g_partial[NCTA * 2048];   // per-CTA sum of tn | in (1 MB)
__device__ float  g_simpart[NCTA];
__device__ float  g_sums[Bc * 2048];        // text_global | image_global (already /S)
__device__ float  g_globalsim[Bc];
__device__ float  g_gates[Bc * Hc * HDc];
__device__ float  g_gate[Bc];
__device__ unsigned g_barcnt = 0;
__device__ unsigned g_bargen = 0;

__device__ __forceinline__ float bfly(float v) {
#pragma unroll
    for (int o = 16; o > 0; o >>= 1) v += __shfl_xor_sync(0xffffffffu, v, o);
    return v;
}

__device__ __forceinline__ uint32_t smem_u32(const void* p) {
    uint32_t a;
    asm("{ .reg .u64 t; cvta.to.shared.u64 t, %1; cvt.u32.u64 %0, t; }" : "=r"(a) : "l"(p));
    return a;
}
__device__ __forceinline__ void mbar_init(uint32_t a, uint32_t cnt) {
    asm volatile("mbarrier.init.shared.b64 [%0], %1;" :: "r"(a), "r"(cnt) : "memory");
}
__device__ __forceinline__ void mbar_expect_tx(uint32_t a, uint32_t bytes) {
    asm volatile("mbarrier.arrive.expect_tx.shared.b64 _, [%0], %1;" :: "r"(a), "r"(bytes) : "memory");
}
__device__ __forceinline__ void bulk_g2s(uint32_t dst, const void* src, uint32_t bytes, uint32_t mbar) {
    asm volatile("cp.async.bulk.shared::cluster.global.mbarrier::complete_tx::bytes [%0], [%1], %2, [%3];"
                 :: "r"(dst), "l"(src), "r"(bytes), "r"(mbar) : "memory");
}
__device__ __forceinline__ void mbar_wait(uint32_t a, uint32_t parity) {
    uint32_t done;
    asm volatile(
        "{\n\t.reg .pred p;\n\t"
        "mbarrier.try_wait.parity.acquire.cta.shared::cta.b64 p, [%1], %2;\n\t"
        "selp.b32 %0, 1, 0, p;\n\t}"
        : "=r"(done) : "r"(a), "r"(parity) : "memory");
    if (!done) {
        asm volatile(
            "{\n\t.reg .pred P1;\n\t"
            "W%=:\n\t"
            "mbarrier.try_wait.parity.acquire.cta.shared::cta.b64 P1, [%0], %1, 0x989680;\n\t"
            "@P1 bra.uni D%=;\n\t"
            "bra.uni W%=;\n\t"
            "D%=:\n\t}"
            :: "r"(a), "r"(parity) : "memory");
    }
}

// Grid-wide barrier. Requires all nblk CTAs co-resident.
__device__ __forceinline__ void grid_barrier(unsigned nblk) {
    __syncthreads();
    if (threadIdx.x == 0) {
        __threadfence();
        const unsigned gen = atomicAdd(&g_bargen, 0u);
        __threadfence();
        if (atomicAdd(&g_barcnt, 1u) == nblk - 1u) {
            atomicExch(&g_barcnt, 0u);
            __threadfence();
            atomicAdd(&g_bargen, 1u);
        } else {
            while (atomicAdd(&g_bargen, 0u) == gen) { }
        }
        __threadfence();
    }
    __syncthreads();
}

// ---------------- pass 1: persistent single-wave bulk-copy pipeline ---------
// CTA bi owns rows [bi*128, bi*128+128) — all inside batch bi/16.
// 16 stages x 8 rows, 3-slot ring; fill once, drain once.
__global__ void __launch_bounds__(256) k_stats(
    const float* __restrict__ xt, const float* __restrict__ xi,
    const float* __restrict__ ltw, const float* __restrict__ ltb,
    const float* __restrict__ liw, const float* __restrict__ lib)
{
    extern __shared__ __align__(1024) char dynsm[];
    float* sm = reinterpret_cast<float*>(dynsm);
    __shared__ float s_sim[8];

    const int tid = threadIdx.x, lane = tid & 31, warp = tid >> 5;
    const int bi = blockIdx.x;
    const int row0 = bi * ROWS_PER_CTA;

    const uint32_t smem_base = smem_u32(dynsm);
    const uint32_t mbb = smem_base + MBAR_BYTE_OFF;

    if (tid == 0) {
#pragma unroll
        for (int r = 0; r < RING; r++) mbar_init(mbb + r * 8, 1);
    }
    for (int j = tid; j < 1024; j += 256) {
        sm[SMW + j]        = ltw[j];
        sm[SMW + 1024 + j] = ltb[j];
        sm[SMW + 2048 + j] = liw[j];
        sm[SMW + 3072 + j] = lib[j];
    }
    __syncthreads();

    const float* srcT = xt + (size_t)row0 * 1024;
    const float* srcI = xi + (size_t)row0 * 1024;

    if (tid == 0) {
#pragma unroll
        for (int s = 0; s < RING; s++) {
            const uint32_t mb = mbb + s * 8;
            mbar_expect_tx(mb, 65536);
            const uint32_t dst = smem_base + (SMBUF + s * STAGE_FLOATS) * 4;
            bulk_g2s(dst,         srcT + s * 8192, 32768, mb);
            bulk_g2s(dst + 32768, srcI + s * 8192, 32768, mb);
        }
    }

    float4 vt[8], vi[8];
#pragma unroll
    for (int g = 0; g < 8; g++) {
        vt[g] = make_float4(0.f, 0.f, 0.f, 0.f);
        vi[g] = make_float4(0.f, 0.f, 0.f, 0.f);
    }
    float sim_acc = 0.f;

    for (int s = 0; s < NSTAGE; s++) {
        const int slot = s % RING;
        const int par  = (s / RING) & 1;
        const uint32_t mb = mbb + slot * 8;
        mbar_wait(mb, par);

        const float* bufT = sm + SMBUF + slot * STAGE_FLOATS + warp * 1024;
        const float4* A4 = reinterpret_cast<const float4*>(bufT);
        const float4* C4 = reinterpret_cast<const float4*>(bufT + 8192);
        const int row = row0 + s * 8 + warp;

        // ---- Phase A: moments ----
        float sa = 0.f, saa = 0.f, sc = 0.f, scc = 0.f;
#pragma unroll
        for (int g = 0; g < 8; g++) {
            const float4 a = A4[g * 32 + lane];
            const float4 c = C4[g * 32 + lane];
            sa += a.x; saa = fmaf(a.x, a.x, saa);
            sa += a.y; saa = fmaf(a.y, a.y, saa);
            sa += a.z; saa = fmaf(a.z, a.z, saa);
            sa += a.w; saa = fmaf(a.w, a.w, saa);
            sc += c.x; scc = fmaf(c.x, c.x, scc);
            sc += c.y; scc = fmaf(c.y, c.y, scc);
            sc += c.z; scc = fmaf(c.z, c.z, scc);
            sc += c.w; scc = fmaf(c.w, c.w, scc);
        }
        sa = bfly(sa); saa = bfly(saa); sc = bfly(sc); scc = bfly(scc);

        const float mut = sa * (1.f / 1024.f);
        const float rt  = rsqrtf(fmaxf(saa * (1.f / 1024.f) - mut * mut, 0.f) + 1e-5f);
        const float mui = sc * (1.f / 1024.f);
        const float ri  = rsqrtf(fmaxf(scc * (1.f / 1024.f) - mui * mui, 0.f) + 1e-5f);
        if (lane == 0) g_rowstats[row] = make_float4(mut, rt, mui, ri);

        // ---- Phase B: normalize, accumulate ----
        const float nmt = -rt * mut, nmi = -ri * mui;
        float tt = 0.f, ii = 0.f, ti = 0.f;
#pragma unroll
        for (int g = 0; g < 8; g++) {
            const float4 a = A4[g * 32 + lane];
            const float4 c = C4[g * 32 + lane];
            const int o = g * 128 + lane * 4;
            const float4 w_t = *reinterpret_cast<const float4*>(&sm[SMW + o]);
            const float4 b_t = *reinterpret_cast<const float4*>(&sm[SMW + 1024 + o]);
            const float4 w_i = *reinterpret_cast<const float4*>(&sm[SMW + 2048 + o]);
            const float4 b_i = *reinterpret_cast<const float4*>(&sm[SMW + 3072 + o]);

            float f, h2, tn, in;
            f  = fmaf(a.x, rt, nmt);  tn = fmaf(f, w_t.x, b_t.x);
            h2 = fmaf(c.x, ri, nmi);  in = fmaf(h2, w_i.x, b_i.x);
            tt = fmaf(tn, tn, tt); ii = fmaf(in, in, ii); ti = fmaf(tn, in, ti);
            vt[g].x += tn; vi[g].x += in;

            f  = fmaf(a.y, rt, nmt);  tn = fmaf(f, w_t.y, b_t.y);
            h2 = fmaf(c.y, ri, nmi);  in = fmaf(h2, w_i.y, b_i.y);
            tt = fmaf(tn, tn, tt); ii = fmaf(in, in, ii); ti = fmaf(tn, in, ti);
            vt[g].y += tn; vi[g].y += in;

            f  = fmaf(a.z, rt, nmt);  tn = fmaf(f, w_t.z, b_t.z);
            h2 = fmaf(c.z, ri, nmi);  in = fmaf(h2, w_i.z, b_i.z);
            tt = fmaf(tn, tn, tt); ii = fmaf(in, in, ii); ti = fmaf(tn, in, ti);
            vt[g].z += tn; vi[g].z += in;

            f  = fmaf(a.w, rt, nmt);  tn = fmaf(f, w_t.w, b_t.w);
            h2 = fmaf(c.w, ri, nmi);  in = fmaf(h2, w_i.w, b_i.w);
            tt = fmaf(tn, tn, tt); ii = fmaf(in, in, ii); ti = fmaf(tn, in, ti);
            vt[g].w += tn; vi[g].w += in;
        }
        tt = bfly(tt); ii = bfly(ii); ti = bfly(ti);
        sim_acc += ti / (fmaxf(sqrtf(tt), 1e-6f) * fmaxf(sqrtf(ii), 1e-6f));

        __syncthreads();   // all warps done with this slot
        if (tid == 0 && s + RING < NSTAGE) {
            const int ns = s + RING;
            mbar_expect_tx(mb, 65536);
            const uint32_t dst = smem_base + (SMBUF + slot * STAGE_FLOATS) * 4;
            bulk_g2s(dst,         srcT + ns * 8192, 32768, mb);
            bulk_g2s(dst + 32768, srcI + ns * 8192, 32768, mb);
        }
    }

    if (lane == 0) s_sim[warp] = sim_acc;
    __syncthreads();    // buffers dead; combine in slot-0 region (4 slices x 2048)

    float* slice = sm + SMBUF + (warp & 3) * 2048;
    if (warp < 4) {
#pragma unroll
        for (int g = 0; g < 8; g++) {
            *reinterpret_cast<float4*>(&slice[g * 128 + lane * 4])        = vt[g];
            *reinterpret_cast<float4*>(&slice[1024 + g * 128 + lane * 4]) = vi[g];
        }
    }
    __syncthreads();
    if (warp >= 4) {
#pragma unroll
        for (int g = 0; g < 8; g++) {
            float4* p = reinterpret_cast<float4*>(&slice[g * 128 + lane * 4]);
            float4 v = *p;
            v.x += vt[g].x; v.y += vt[g].y; v.z += vt[g].z; v.w += vt[g].w;
            *p = v;
            float4* q = reinterpret_cast<float4*>(&slice[1024 + g * 128 + lane * 4]);
            float4 u = *q;
            u.x += vi[g].x; u.y += vi[g].y; u.z += vi[g].z; u.w += vi[g].w;
            *q = u;
        }
    }
    __syncthreads();
    for (int j = tid; j < 2048; j += 256)
        g_partial[bi * 2048 + j] = (sm[SMBUF + j] + sm[SMBUF + 2048 + j])
                                 + (sm[SMBUF + 4096 + j] + sm[SMBUF + 6144 + j]);
    if (tid == 0) {
        float s = 0.f;
#pragma unroll
        for (int w = 0; w < 8; w++) s += s_sim[w];
        g_simpart[bi] = s;
    }
}

// ---------------- pass 2 (fused): reduce -> gates -> fc ---------------------
__global__ void __launch_bounds__(256) k_mid(
    const float* __restrict__ Wa, const float* __restrict__ Wab,
    const float* __restrict__ Wq, const float* __restrict__ Wqb,
    const float* __restrict__ simw, const float* __restrict__ simb,
    const float* __restrict__ fcw, const float* __restrict__ fcb)
{
    const int tid = threadIdx.x, bi = blockIdx.x;
    const int warp = tid >> 5, lane = tid & 31;
    __shared__ float red[256];

    // ---- Phase A: fold 16 partials per slot (128 slots per block) ----
    {
        const int j = bi * 128 + (tid & 127);       // global slot 0..16383
        const int half = tid >> 7;                  // 0 or 1
        const int b = j >> 11, slot = j & 2047;
        float s = 0.f;
#pragma unroll
        for (int p = half * 8; p < half * 8 + 8; p++)
            s += g_partial[(b * 16 + p) * 2048 + slot];
        red[tid] = s;
        __syncthreads();
        if (tid < 128) g_sums[j] = (red[tid] + red[tid + 128]) * (1.f / (float)Sc);
    }
    if (bi == 0) {   // sim reduce: warp w handles batch w (16 CTAs each)
        float v = (lane < 16) ? g_simpart[warp * 16 + lane] : 0.f;
        v = bfly(v);
        if (lane == 0) g_globalsim[warp] = v * (1.f / (float)Sc);
    }

    grid_barrier(MIDBLK);

    // ---- Phase B: gate GEMV, warp-per-hk, all 8 batches per warp ----
    {
        const int hk = bi * 8 + warp;      // 0..1023
        const int k  = hk & 255;

        const float4* wa = reinterpret_cast<const float4*>(Wa + (size_t)hk * 1024);
        const float4* wq = reinterpret_cast<const float4*>(Wq + (size_t)hk * 1024);

        float4 wA[8], wQ[8];
#pragma unroll
        for (int g = 0; g < 8; g++) {
            wA[g] = __ldg(&wa[g * 32 + lane]);
            wQ[g] = __ldg(&wq[g * 32 + lane]);
        }

        float da[Bc], dq[Bc];
#pragma unroll
        for (int b = 0; b < Bc; b++) { da[b] = 0.f; dq[b] = 0.f; }

#pragma unroll
        for (int b = 0; b < Bc; b++) {
            const float4* tg = reinterpret_cast<const float4*>(g_sums + b * 2048);
            const float4* ig = tg + 256;
#pragma unroll
            for (int g = 0; g < 8; g++) {
                const float4 t = __ldg(&tg[g * 32 + lane]);
                const float4 i = __ldg(&ig[g * 32 + lane]);
                da[b] = fmaf(wA[g].x, t.x, da[b]); da[b] = fmaf(wA[g].y, t.y, da[b]);
                da[b] = fmaf(wA[g].z, t.z, da[b]); da[b] = fmaf(wA[g].w, t.w, da[b]);
                dq[b] = fmaf(wQ[g].x, i.x, dq[b]); dq[b] = fmaf(wQ[g].y, i.y, dq[b]);
                dq[b] = fmaf(wQ[g].z, i.z, dq[b]); dq[b] = fmaf(wQ[g].w, i.w, dq[b]);
            }
        }
#pragma unroll
        for (int b = 0; b < Bc; b++) { da[b] = bfly(da[b]); dq[b] = bfly(dq[b]); }

        if (lane == 0) {
            const float wab = Wab[hk], wqb = Wqb[hk];
            const float sw = simw[k], sb = simb[k];
#pragma unroll
            for (int b = 0; b < Bc; b++) {
                const float gate = da[b] + wab + dq[b] + wqb + g_globalsim[b] * sw + sb;
                g_gates[b * 1024 + hk] = fmaxf(gate, 0.f);
            }
        }
    }

    grid_barrier(MIDBLK);

    // ---- Phase C: fc dot + sigmoid, blocks 0..7 ----
    if (bi < Bc) {
        float acc = 0.f;
#pragma unroll
        for (int k = tid; k < 1024; k += 256) acc += g_gates[bi * 1024 + k] * fcw[k];
        acc = bfly(acc);
        if (lane == 0) red[warp] = acc;
        __syncthreads();
        if (tid == 0) {
            float s = 0.f;
#pragma unroll
            for (int w = 0; w < 8; w++) s += red[w];
            g_gate[bi] = 1.0f / (1.0f + expf(-(s + fcb[0])));
        }
    }
}

// ---------------- pass 3: out = g*LN(t) + (1-g)*LN(i) -----------------------
__global__ void __launch_bounds__(256) k_out(
    const float* __restrict__ xt, const float* __restrict__ xi,
    const float* __restrict__ ltw, const float* __restrict__ ltb,
    const float* __restrict__ liw, const float* __restrict__ lib,
    float* __restrict__ out)
{
    const int t = threadIdx.x;
    const float4 wt = reinterpret_cast<const float4*>(ltw)[t];
    const float4 bt = reinterpret_cast<const float4*>(ltb)[t];
    const float4 wi = reinterpret_cast<const float4*>(liw)[t];
    const float4 bi = reinterpret_cast<const float4*>(lib)[t];
    const float4* xt4 = reinterpret_cast<const float4*>(xt);
    const float4* xi4 = reinterpret_cast<const float4*>(xi);
    float4* o4 = reinterpret_cast<float4*>(out);

    const int row0 = (int)blockIdx.x * 4;
#pragma unroll
    for (int r = 0; r < 4; r++) {
        const int row = row0 + r;
        const float4 rs = g_rowstats[row];
        const float g  = g_gate[row >> 11];
        const float gm = 1.0f - g;
        const int idx  = row * 256 + t;
        const float4 a = __ldcs(&xt4[idx]);
        const float4 c = __ldcs(&xi4[idx]);
        float4 o;
        o.x = g * ((a.x - rs.x) * rs.y * wt.x + bt.x) + gm * ((c.x - rs.z) * rs.w * wi.x + bi.x);
        o.y = g * ((a.y - rs.x) * rs.y * wt.y + bt.y) + gm * ((c.y - rs.z) * rs.w * wi.y + bi.y);
        o.z = g * ((a.z - rs.x) * rs.y * wt.z + bt.z) + gm * ((c.z - rs.z) * rs.w * wi.z + bi.z);
        o.w = g * ((a.w - rs.x) * rs.y * wt.w + bt.w) + gm * ((c.w - rs.z) * rs.w * wi.w + bi.w);
        __stcs(&o4[idx], o);
    }
}

// ---------------- launch -----------------------------------------------------
extern "C" void kernel_launch(void* const* d_in, const int* in_sizes, int n_in,
                              void* d_out, int out_size)
{
    const float* xt   = (const float*)d_in[0];
    const float* xi   = (const float*)d_in[1];
    const float* ltw  = (const float*)d_in[2];
    const float* ltb  = (const float*)d_in[3];
    const float* liw  = (const float*)d_in[4];
    const float* lib  = (const float*)d_in[5];
    const float* Wa   = (const float*)d_in[6];
    const float* Wab  = (const float*)d_in[7];
    const float* Wq   = (const float*)d_in[8];
    const float* Wqb  = (const float*)d_in[9];
    const float* simw = (const float*)d_in[10];
    const float* simb = (const float*)d_in[11];
    const float* fcw  = (const float*)d_in[12];
    const float* fcb  = (const float*)d_in[13];
    float* out = (float*)d_out;

    static bool attr_set = false;
    if (!attr_set) {
        cudaFuncSetAttribute(k_stats, cudaFuncAttributeMaxDynamicSharedMemorySize, SMEM_BYTES);
        attr_set = true;
    }

    k_stats<<<NCTA, 256, SMEM_BYTES>>>(xt, xi, ltw, ltb, liw, lib);
    k_mid  <<<MIDBLK, 256>>>(Wa, Wab, Wq, Wqb, simw, simb, fcw, fcb);
    k_out  <<<(Bc * Sc) / 4, 256>>>(xt, xi, ltw, ltb, liw, lib, out);
}

// round 9
// speedup vs baseline: 1.1495x; 1.0083x over previous
#include <cuda_runtime.h>
#include <math.h>
#include <stdint.h>

#define Bc 8
#define Sc 2048
#define Dc 1024
#define Hc 4
#define HDc 256
#define NCTA 128                 // persistent single-wave grid for k_stats
#define ROWS_PER_CTA 128
#define NSTAGE 16                // 16 stages x 8 rows
#define RING 3
#define MIDBLK 128

// k_stats dynamic smem: 3 ring slots x (2 tensors x 8 rows x 1024 f) = 192 KB; mbarriers at tail.
#define STAGE_FLOATS 16384
#define MBAR_BYTE_OFF (RING * STAGE_FLOATS * 4)   // 196608
#define SMEM_BYTES (MBAR_BYTE_OFF + 64)

// ---------------- scratch (static device memory; no allocation) -------------
__device__ float4 g_rowstats[Bc * Sc];
__device__ float  g_partial[NCTA * 2048];
__device__ float  g_simpart[NCTA];
__device__ float  g_sums[Bc * 2048];
__device__ float  g_globalsim[Bc];
__device__ float  g_gates[Bc * Hc * HDc];
__device__ float  g_gate[Bc];
__device__ unsigned g_barcnt = 0;
__device__ unsigned g_bargen = 0;

__device__ __forceinline__ float bfly(float v) {
#pragma unroll
    for (int o = 16; o > 0; o >>= 1) v += __shfl_xor_sync(0xffffffffu, v, o);
    return v;
}

__device__ __forceinline__ uint32_t smem_u32(const void* p) {
    uint32_t a;
    asm("{ .reg .u64 t; cvta.to.shared.u64 t, %1; cvt.u32.u64 %0, t; }" : "=r"(a) : "l"(p));
    return a;
}
__device__ __forceinline__ void mbar_init(uint32_t a, uint32_t cnt) {
    asm volatile("mbarrier.init.shared.b64 [%0], %1;" :: "r"(a), "r"(cnt) : "memory");
}
__device__ __forceinline__ void mbar_expect_tx(uint32_t a, uint32_t bytes) {
    asm volatile("mbarrier.arrive.expect_tx.shared.b64 _, [%0], %1;" :: "r"(a), "r"(bytes) : "memory");
}
__device__ __forceinline__ void bulk_g2s(uint32_t dst, const void* src, uint32_t bytes, uint32_t mbar) {
    asm volatile("cp.async.bulk.shared::cluster.global.mbarrier::complete_tx::bytes [%0], [%1], %2, [%3];"
                 :: "r"(dst), "l"(src), "r"(bytes), "r"(mbar) : "memory");
}
__device__ __forceinline__ void mbar_wait(uint32_t a, uint32_t parity) {
    uint32_t done;
    asm volatile(
        "{\n\t.reg .pred p;\n\t"
        "mbarrier.try_wait.parity.acquire.cta.shared::cta.b64 p, [%1], %2;\n\t"
        "selp.b32 %0, 1, 0, p;\n\t}"
        : "=r"(done) : "r"(a), "r"(parity) : "memory");
    if (!done) {
        asm volatile(
            "{\n\t.reg .pred P1;\n\t"
            "W%=:\n\t"
            "mbarrier.try_wait.parity.acquire.cta.shared::cta.b64 P1, [%0], %1, 0x989680;\n\t"
            "@P1 bra.uni D%=;\n\t"
            "bra.uni W%=;\n\t"
            "D%=:\n\t}"
            :: "r"(a), "r"(parity) : "memory");
    }
}

// Grid-wide barrier. Requires all nblk CTAs co-resident.
__device__ __forceinline__ void grid_barrier(unsigned nblk) {
    __syncthreads();
    if (threadIdx.x == 0) {
        __threadfence();
        const unsigned gen = atomicAdd(&g_bargen, 0u);
        __threadfence();
        if (atomicAdd(&g_barcnt, 1u) == nblk - 1u) {
            atomicExch(&g_barcnt, 0u);
            __threadfence();
            atomicAdd(&g_bargen, 1u);
        } else {
            while (atomicAdd(&g_bargen, 0u) == gen) { }
        }
        __threadfence();
    }
    __syncthreads();
}

// ---------------- pass 1: persistent pipeline, 2-warps-per-row, reg weights -
// Warp pair owns a row; thread owns 16 fixed columns (weights in registers).
// Each stage: 8 rows, pair handles 2. Data read from smem exactly once.
__global__ void __launch_bounds__(256) k_stats(
    const float* __restrict__ xt, const float* __restrict__ xi,
    const float* __restrict__ ltw, const float* __restrict__ ltb,
    const float* __restrict__ liw, const float* __restrict__ lib)
{
    extern __shared__ __align__(1024) char dynsm[];
    float* sm = reinterpret_cast<float*>(dynsm);
    __shared__ float4 redA[4][2];
    __shared__ float4 redB[4][2];
    __shared__ float s_sim[4];

    const int tid = threadIdx.x, lane = tid & 31, warp = tid >> 5;
    const int pair = warp >> 1, h = warp & 1;
    const int bi = blockIdx.x;
    const int row0 = bi * ROWS_PER_CTA;
    const int cidx = h * 128 + lane;            // thread's float4-column base (+ g*32)

    const uint32_t smem_base = smem_u32(dynsm);
    const uint32_t mbb = smem_base + MBAR_BYTE_OFF;

    // weights: 16 float4 in registers, loaded once
    float4 w_t[4], b_t[4], w_i[4], b_i[4];
#pragma unroll
    for (int g = 0; g < 4; g++) {
        w_t[g] = __ldg(&reinterpret_cast<const float4*>(ltw)[cidx + g * 32]);
        b_t[g] = __ldg(&reinterpret_cast<const float4*>(ltb)[cidx + g * 32]);
        w_i[g] = __ldg(&reinterpret_cast<const float4*>(liw)[cidx + g * 32]);
        b_i[g] = __ldg(&reinterpret_cast<const float4*>(lib)[cidx + g * 32]);
    }

    if (tid == 0) {
#pragma unroll
        for (int r = 0; r < RING; r++) mbar_init(mbb + r * 8, 1);
    }
    __syncthreads();

    const float* srcT = xt + (size_t)row0 * 1024;
    const float* srcI = xi + (size_t)row0 * 1024;

    if (tid == 0) {
#pragma unroll
        for (int s = 0; s < RING; s++) {
            const uint32_t mb = mbb + s * 8;
            mbar_expect_tx(mb, 65536);
            const uint32_t dst = smem_base + s * STAGE_FLOATS * 4;
            bulk_g2s(dst,         srcT + s * 8192, 32768, mb);
            bulk_g2s(dst + 32768, srcI + s * 8192, 32768, mb);
        }
    }

    float4 vt[4], vi[4];
#pragma unroll
    for (int g = 0; g < 4; g++) {
        vt[g] = make_float4(0.f, 0.f, 0.f, 0.f);
        vi[g] = make_float4(0.f, 0.f, 0.f, 0.f);
    }
    float sim_acc = 0.f;

    for (int s = 0; s < NSTAGE; s++) {
        const int slot = s % RING;
        const int par  = (s / RING) & 1;
        mbar_wait(mbb + slot * 8, par);
        const float* buf = sm + slot * STAGE_FLOATS;

#pragma unroll
        for (int rr = 0; rr < 2; rr++) {
            const int rlocal = pair * 2 + rr;
            const int row = row0 + s * 8 + rlocal;
            const float4* A4 = reinterpret_cast<const float4*>(buf + rlocal * 1024);
            const float4* C4 = reinterpret_cast<const float4*>(buf + 8192 + rlocal * 1024);

            // single smem read of this thread's 16+16 elements, kept in regs
            float4 A[4], C[4];
#pragma unroll
            for (int g = 0; g < 4; g++) {
                A[g] = A4[cidx + g * 32];
                C[g] = C4[cidx + g * 32];
            }

            // ---- moments over half-row, then pair combine ----
            float sa = 0.f, saa = 0.f, sc = 0.f, scc = 0.f;
#pragma unroll
            for (int g = 0; g < 4; g++) {
                sa += A[g].x; saa = fmaf(A[g].x, A[g].x, saa);
                sa += A[g].y; saa = fmaf(A[g].y, A[g].y, saa);
                sa += A[g].z; saa = fmaf(A[g].z, A[g].z, saa);
                sa += A[g].w; saa = fmaf(A[g].w, A[g].w, saa);
                sc += C[g].x; scc = fmaf(C[g].x, C[g].x, scc);
                sc += C[g].y; scc = fmaf(C[g].y, C[g].y, scc);
                sc += C[g].z; scc = fmaf(C[g].z, C[g].z, scc);
                sc += C[g].w; scc = fmaf(C[g].w, C[g].w, scc);
            }
            sa = bfly(sa); saa = bfly(saa); sc = bfly(sc); scc = bfly(scc);
            if (lane == 0) redA[pair][h] = make_float4(sa, saa, sc, scc);
            __syncthreads();
            const float4 e0 = redA[pair][0], e1 = redA[pair][1];
            const float mut = (e0.x + e1.x) * (1.f / 1024.f);
            const float rt  = rsqrtf(fmaxf((e0.y + e1.y) * (1.f / 1024.f) - mut * mut, 0.f) + 1e-5f);
            const float mui = (e0.z + e1.z) * (1.f / 1024.f);
            const float ri  = rsqrtf(fmaxf((e0.w + e1.w) * (1.f / 1024.f) - mui * mui, 0.f) + 1e-5f);
            if (h == 0 && lane == 0) g_rowstats[row] = make_float4(mut, rt, mui, ri);

            // ---- normalize from regs with reg weights, accumulate ----
            const float nmt = -rt * mut, nmi = -ri * mui;
            float tt = 0.f, ii = 0.f, ti = 0.f;
#pragma unroll
            for (int g = 0; g < 4; g++) {
                float f, h2, tn, in;
                f  = fmaf(A[g].x, rt, nmt);  tn = fmaf(f, w_t[g].x, b_t[g].x);
                h2 = fmaf(C[g].x, ri, nmi);  in = fmaf(h2, w_i[g].x, b_i[g].x);
                tt = fmaf(tn, tn, tt); ii = fmaf(in, in, ii); ti = fmaf(tn, in, ti);
                vt[g].x += tn; vi[g].x += in;

                f  = fmaf(A[g].y, rt, nmt);  tn = fmaf(f, w_t[g].y, b_t[g].y);
                h2 = fmaf(C[g].y, ri, nmi);  in = fmaf(h2, w_i[g].y, b_i[g].y);
                tt = fmaf(tn, tn, tt); ii = fmaf(in, in, ii); ti = fmaf(tn, in, ti);
                vt[g].y += tn; vi[g].y += in;

                f  = fmaf(A[g].z, rt, nmt);  tn = fmaf(f, w_t[g].z, b_t[g].z);
                h2 = fmaf(C[g].z, ri, nmi);  in = fmaf(h2, w_i[g].z, b_i[g].z);
                tt = fmaf(tn, tn, tt); ii = fmaf(in, in, ii); ti = fmaf(tn, in, ti);
                vt[g].z += tn; vi[g].z += in;

                f  = fmaf(A[g].w, rt, nmt);  tn = fmaf(f, w_t[g].w, b_t[g].w);
                h2 = fmaf(C[g].w, ri, nmi);  in = fmaf(h2, w_i[g].w, b_i[g].w);
                tt = fmaf(tn, tn, tt); ii = fmaf(in, in, ii); ti = fmaf(tn, in, ti);
                vt[g].w += tn; vi[g].w += in;
            }
            tt = bfly(tt); ii = bfly(ii); ti = bfly(ti);
            if (lane == 0) redB[pair][h] = make_float4(tt, ii, ti, 0.f);
            __syncthreads();   // after this, all slot reads for rr done block-wide
            if (h == 0) {
                const float4 d0 = redB[pair][0], d1 = redB[pair][1];
                sim_acc += (d0.z + d1.z) /
                           (fmaxf(sqrtf(d0.x + d1.x), 1e-6f) * fmaxf(sqrtf(d0.y + d1.y), 1e-6f));
            }
        }

        // slot fully consumed (last __syncthreads above); reissue
        if (tid == 0 && s + RING < NSTAGE) {
            const int ns = s + RING;
            const uint32_t mb = mbb + slot * 8;
            mbar_expect_tx(mb, 65536);
            const uint32_t dst = smem_base + slot * STAGE_FLOATS * 4;
            bulk_g2s(dst,         srcT + ns * 8192, 32768, mb);
            bulk_g2s(dst + 32768, srcI + ns * 8192, 32768, mb);
        }
    }

    if (h == 0 && lane == 0) s_sim[pair] = sim_acc;
    __syncthreads();    // buffers dead; combine in slot-0 region (2 slices x 2048)

    float4* slice = reinterpret_cast<float4*>(sm + (pair & 1) * 2048);
    if (pair < 2) {
#pragma unroll
        for (int g = 0; g < 4; g++) {
            slice[cidx + g * 32]       = vt[g];
            slice[256 + cidx + g * 32] = vi[g];
        }
    }
    __syncthreads();
    if (pair >= 2) {
#pragma unroll
        for (int g = 0; g < 4; g++) {
            float4 v = slice[cidx + g * 32];
            v.x += vt[g].x; v.y += vt[g].y; v.z += vt[g].z; v.w += vt[g].w;
            slice[cidx + g * 32] = v;
            float4 u = slice[256 + cidx + g * 32];
            u.x += vi[g].x; u.y += vi[g].y; u.z += vi[g].z; u.w += vi[g].w;
            slice[256 + cidx + g * 32] = u;
        }
    }
    __syncthreads();
    for (int j = tid; j < 2048; j += 256)
        g_partial[bi * 2048 + j] = sm[j] + sm[2048 + j];
    if (tid == 0)
        g_simpart[bi] = (s_sim[0] + s_sim[1]) + (s_sim[2] + s_sim[3]);
}

// ---------------- pass 2 (fused): reduce -> gates -> fc ---------------------
__global__ void __launch_bounds__(256) k_mid(
    const float* __restrict__ Wa, const float* __restrict__ Wab,
    const float* __restrict__ Wq, const float* __restrict__ Wqb,
    const float* __restrict__ simw, const float* __restrict__ simb,
    const float* __restrict__ fcw, const float* __restrict__ fcb)
{
    const int tid = threadIdx.x, bi = blockIdx.x;
    const int warp = tid >> 5, lane = tid & 31;
    __shared__ float red[256];

    {
        const int j = bi * 128 + (tid & 127);
        const int half = tid >> 7;
        const int b = j >> 11, slot = j & 2047;
        float s = 0.f;
#pragma unroll
        for (int p = half * 8; p < half * 8 + 8; p++)
            s += g_partial[(b * 16 + p) * 2048 + slot];
        red[tid] = s;
        __syncthreads();
        if (tid < 128) g_sums[j] = (red[tid] + red[tid + 128]) * (1.f / (float)Sc);
    }
    if (bi == 0) {
        float v = (lane < 16) ? g_simpart[warp * 16 + lane] : 0.f;
        v = bfly(v);
        if (lane == 0) g_globalsim[warp] = v * (1.f / (float)Sc);
    }

    grid_barrier(MIDBLK);

    {
        const int hk = bi * 8 + warp;
        const int k  = hk & 255;

        const float4* wa = reinterpret_cast<const float4*>(Wa + (size_t)hk * 1024);
        const float4* wq = reinterpret_cast<const float4*>(Wq + (size_t)hk * 1024);

        float4 wA[8], wQ[8];
#pragma unroll
        for (int g = 0; g < 8; g++) {
            wA[g] = __ldg(&wa[g * 32 + lane]);
            wQ[g] = __ldg(&wq[g * 32 + lane]);
        }

        float da[Bc], dq[Bc];
#pragma unroll
        for (int b = 0; b < Bc; b++) { da[b] = 0.f; dq[b] = 0.f; }

#pragma unroll
        for (int b = 0; b < Bc; b++) {
            const float4* tg = reinterpret_cast<const float4*>(g_sums + b * 2048);
            const float4* ig = tg + 256;
#pragma unroll
            for (int g = 0; g < 8; g++) {
                const float4 t = __ldg(&tg[g * 32 + lane]);
                const float4 i = __ldg(&ig[g * 32 + lane]);
                da[b] = fmaf(wA[g].x, t.x, da[b]); da[b] = fmaf(wA[g].y, t.y, da[b]);
                da[b] = fmaf(wA[g].z, t.z, da[b]); da[b] = fmaf(wA[g].w, t.w, da[b]);
                dq[b] = fmaf(wQ[g].x, i.x, dq[b]); dq[b] = fmaf(wQ[g].y, i.y, dq[b]);
                dq[b] = fmaf(wQ[g].z, i.z, dq[b]); dq[b] = fmaf(wQ[g].w, i.w, dq[b]);
            }
        }
#pragma unroll
        for (int b = 0; b < Bc; b++) { da[b] = bfly(da[b]); dq[b] = bfly(dq[b]); }

        if (lane == 0) {
            const float wab = Wab[hk], wqb = Wqb[hk];
            const float sw = simw[k], sb = simb[k];
#pragma unroll
            for (int b = 0; b < Bc; b++) {
                const float gate = da[b] + wab + dq[b] + wqb + g_globalsim[b] * sw + sb;
                g_gates[b * 1024 + hk] = fmaxf(gate, 0.f);
            }
        }
    }

    grid_barrier(MIDBLK);

    if (bi < Bc) {
        float acc = 0.f;
#pragma unroll
        for (int k = tid; k < 1024; k += 256) acc += g_gates[bi * 1024 + k] * fcw[k];
        acc = bfly(acc);
        if (lane == 0) red[warp] = acc;
        __syncthreads();
        if (tid == 0) {
            float s = 0.f;
#pragma unroll
            for (int w = 0; w < 8; w++) s += red[w];
            g_gate[bi] = 1.0f / (1.0f + expf(-(s + fcb[0])));
        }
    }
}

// ---------------- pass 3: out = g*LN(t) + (1-g)*LN(i) -----------------------
__global__ void __launch_bounds__(256) k_out(
    const float* __restrict__ xt, const float* __restrict__ xi,
    const float* __restrict__ ltw, const float* __restrict__ ltb,
    const float* __restrict__ liw, const float* __restrict__ lib,
    float* __restrict__ out)
{
    const int t = threadIdx.x;
    const float4 wt = reinterpret_cast<const float4*>(ltw)[t];
    const float4 bt = reinterpret_cast<const float4*>(ltb)[t];
    const float4 wi = reinterpret_cast<const float4*>(liw)[t];
    const float4 bi = reinterpret_cast<const float4*>(lib)[t];
    const float4* xt4 = reinterpret_cast<const float4*>(xt);
    const float4* xi4 = reinterpret_cast<const float4*>(xi);
    float4* o4 = reinterpret_cast<float4*>(out);

    const int row0 = (int)blockIdx.x * 4;
#pragma unroll
    for (int r = 0; r < 4; r++) {
        const int row = row0 + r;
        const float4 rs = g_rowstats[row];
        const float g  = g_gate[row >> 11];
        const float gm = 1.0f - g;
        const int idx  = row * 256 + t;
        const float4 a = __ldcs(&xt4[idx]);
        const float4 c = __ldcs(&xi4[idx]);
        float4 o;
        o.x = g * ((a.x - rs.x) * rs.y * wt.x + bt.x) + gm * ((c.x - rs.z) * rs.w * wi.x + bi.x);
        o.y = g * ((a.y - rs.x) * rs.y * wt.y + bt.y) + gm * ((c.y - rs.z) * rs.w * wi.y + bi.y);
        o.z = g * ((a.z - rs.x) * rs.y * wt.z + bt.z) + gm * ((c.z - rs.z) * rs.w * wi.z + bi.z);
        o.w = g * ((a.w - rs.x) * rs.y * wt.w + bt.w) + gm * ((c.w - rs.z) * rs.w * wi.w + bi.w);
        __stcs(&o4[idx], o);
    }
}

// ---------------- launch -----------------------------------------------------
extern "C" void kernel_launch(void* const* d_in, const int* in_sizes, int n_in,
                              void* d_out, int out_size)
{
    const float* xt   = (const float*)d_in[0];
    const float* xi   = (const float*)d_in[1];
    const float* ltw  = (const float*)d_in[2];
    const float* ltb  = (const float*)d_in[3];
    const float* liw  = (const float*)d_in[4];
    const float* lib  = (const float*)d_in[5];
    const float* Wa   = (const float*)d_in[6];
    const float* Wab  = (const float*)d_in[7];
    const float* Wq   = (const float*)d_in[8];
    const float* Wqb  = (const float*)d_in[9];
    const float* simw = (const float*)d_in[10];
    const float* simb = (const float*)d_in[11];
    const float* fcw  = (const float*)d_in[12];
    const float* fcb  = (const float*)d_in[13];
    float* out = (float*)d_out;

    static bool attr_set = false;
    if (!attr_set) {
        cudaFuncSetAttribute(k_stats, cudaFuncAttributeMaxDynamicSharedMemorySize, SMEM_BYTES);
        attr_set = true;
    }

    k_stats<<<NCTA, 256, SMEM_BYTES>>>(xt, xi, ltw, ltb, liw, lib);
    k_mid  <<<MIDBLK, 256>>>(Wa, Wab, Wq, Wqb, simw, simb, fcw, fcb);
    k_out  <<<(Bc * Sc) / 4, 256>>>(xt, xi, ltw, ltb, liw, lib, out);
}